// round 5
// baseline (speedup 1.0000x reference)
#include <cuda_runtime.h>
#include <cstdint>

#define Bq 32
#define Tq 1024
#define Iq 64
#define Hq 512
#define Aq 16

#define OUT_N  (Bq*Tq*Aq)          // 524288
#define HN_N   (Bq*Hq)             // 16384
#define HN_OFF OUT_N
#define RNN_OFF (OUT_N + HN_N)     // 540672

#define CLU 8                      // CTAs per cluster
#define NCL 16                     // clusters (16*8 = 128 CTAs)
#define NB  2                      // batches per cluster
#define TXB 4096                   // bytes per mbarrier phase: 8 CTAs * 64 * 8B
#define HROW 528                   // skewed h row stride (floats)
#define HBUF (NB*HROW)             // 1056 floats per buffer

typedef unsigned long long u64;

// ---- scratch (static device globals: allocation-free) ----
__device__ float g_xp[Tq*Bq*Hq];               // x_proj [t][b][j]   (64 MB)
__device__ float g_hidden[(size_t)Bq*Tq*Hq];   // fc1 output (64 MB)

// ================= helpers =================
__device__ __forceinline__ uint32_t smem_u32(const void* p) {
    uint32_t a;
    asm("{ .reg .u64 t; cvta.to.shared.u64 t, %1; cvt.u32.u64 %0, t; }" : "=r"(a) : "l"(p));
    return a;
}
__device__ __forceinline__ uint32_t mapa_u32(uint32_t laddr, uint32_t rank) {
    uint32_t r;
    asm("mapa.shared::cluster.u32 %0, %1, %2;" : "=r"(r) : "r"(laddr), "r"(rank));
    return r;
}
__device__ __forceinline__ void st_async_b64(uint32_t raddr, u64 v, uint32_t rmbar) {
    asm volatile("st.async.shared::cluster.mbarrier::complete_tx::bytes.b64 [%0], %1, [%2];"
                 :: "r"(raddr), "l"(v), "r"(rmbar) : "memory");
}
__device__ __forceinline__ void mbar_init(uint32_t mbar, uint32_t cnt) {
    asm volatile("mbarrier.init.shared.b64 [%0], %1;" :: "r"(mbar), "r"(cnt) : "memory");
}
__device__ __forceinline__ void mbar_arrive_expect_tx(uint32_t mbar, uint32_t tx) {
    asm volatile("mbarrier.arrive.expect_tx.shared.b64 _, [%0], %1;" :: "r"(mbar), "r"(tx) : "memory");
}
__device__ __forceinline__ void mbar_wait_parity(uint32_t mbar, uint32_t parity) {
    asm volatile(
        "{\n\t"
        ".reg .pred P1;\n\t"
        "WAIT_LOOP_%=:\n\t"
        "mbarrier.try_wait.parity.acquire.cta.shared::cta.b64 P1, [%0], %1, 0x989680;\n\t"
        "@P1 bra.uni WAIT_DONE_%=;\n\t"
        "bra.uni WAIT_LOOP_%=;\n\t"
        "WAIT_DONE_%=:\n\t"
        "}" :: "r"(mbar), "r"(parity) : "memory");
}
// packed f32x2 on 64-bit carriers: no per-call repacking
__device__ __forceinline__ u64 ffma2(u64 a, u64 b, u64 c) {
    u64 d;
    asm("fma.rn.f32x2 %0, %1, %2, %3;" : "=l"(d) : "l"(a), "l"(b), "l"(c));
    return d;
}
__device__ __forceinline__ u64 packf2(float x, float y) {
    u64 r; asm("mov.b64 %0, {%1,%2};" : "=l"(r) : "f"(x), "f"(y)); return r;
}
__device__ __forceinline__ float2 unpackf2(u64 v) {
    float2 f; asm("mov.b64 {%0,%1}, %2;" : "=f"(f.x), "=f"(f.y) : "l"(v)); return f;
}
__device__ __forceinline__ float hsum2(u64 v) { float2 f = unpackf2(v); return f.x + f.y; }

// ---------------- x_proj: xp[t][b][j] = sum_i inp[b][t][i] * w_ih[i][j] ----------------
__global__ void __launch_bounds__(512) xp_kernel(const float* __restrict__ inp,
                                                 const float* __restrict__ w_ih) {
    const int b   = blockIdx.x;   // 32
    const int tc  = blockIdx.y;   // 32 chunks of 32 timesteps
    const int tid = threadIdx.x;  // 512 (j)
    __shared__ __align__(16) float s_in[32*64];
    const float* src = inp + (size_t)b*Tq*Iq + (size_t)tc*32*Iq;
    ((float4*)s_in)[tid] = ((const float4*)src)[tid];
    __syncthreads();

    u64 acc[32];
    #pragma unroll
    for (int tt = 0; tt < 32; tt++) acc[tt] = 0ull;

    #pragma unroll 4
    for (int ip = 0; ip < 32; ip++) {           // k-pair over i
        u64 wpk = packf2(w_ih[(2*ip)*Hq + tid], w_ih[(2*ip + 1)*Hq + tid]);
        #pragma unroll
        for (int tt = 0; tt < 32; tt++)
            acc[tt] = ffma2(*(const u64*)&s_in[tt*64 + 2*ip], wpk, acc[tt]);
    }
    #pragma unroll
    for (int tt = 0; tt < 32; tt++)
        g_xp[(size_t)(tc*32 + tt)*(Bq*Hq) + b*Hq + tid] = hsum2(acc[tt]);
}

// ---------------- RNN scan: 16 clusters of 8 CTAs, 512 threads, no in-loop bars ----------------
// lane l: s = l>>2 (k-segment 0..7, 64 k each), q = l&3. warp w owns cols [w*4, w*4+4).
// Each lane: 1 column x 2 batches. Weights: 32 u64 in regs. h skewed in SMEM:
// HSK(k) = k + (k>>6)*2 -> segment s starts at s*66 (broadcast-friendly LDS.64).
__global__ void __launch_bounds__(512, 1) __cluster_dims__(CLU, 1, 1)
rnn_kernel(const float* __restrict__ hn, const float* __restrict__ w_hh,
           float* __restrict__ outbuf) {
    __shared__ __align__(16) float h_s[2][HBUF];           // [buf][b*528 + HSK(k)]
    __shared__ __align__(8)  unsigned long long mbar_s[2];

    const int tid = threadIdx.x;
    uint32_t rank;
    asm("mov.u32 %0, %%cluster_ctarank;" : "=r"(rank));
    const int cid = blockIdx.x >> 3;
    const int j0  = (int)rank * 64;
    const int w   = tid >> 5;
    const int l   = tid & 31;
    const int s   = l >> 2;           // k-segment
    const int q   = l & 3;
    const int c0  = w*4 + q;          // local column (one per lane)
    const int kb  = s * 64;

    // ---- stationary weights: Wp[m] = (w_hh[kb+2m][j0+c0], w_hh[kb+2m+1][j0+c0]) ----
    u64 Wp[32];
    {
        const float* wb = w_hh + (size_t)kb*Hq + j0 + c0;
        #pragma unroll
        for (int m = 0; m < 32; m++)
            Wp[m] = packf2(wb[(size_t)(2*m)*Hq], wb[(size_t)(2*m + 1)*Hq]);
    }
    // ---- h0 into buffer 0 (skewed) ----
    for (int e = tid; e < NB*Hq; e += 512) {
        int b = e >> 9, k = e & 511;
        h_s[0][b*HROW + k + ((k >> 6) << 1)] = hn[(size_t)(cid*NB + b)*Hq + k];
    }
    const uint32_t mbar0 = smem_u32(&mbar_s[0]);
    if (tid == 0) { mbar_init(mbar0, 1); mbar_init(mbar0 + 8, 1); }
    __syncthreads();
    asm volatile("barrier.cluster.arrive.aligned;" ::: "memory");
    asm volatile("barrier.cluster.wait.aligned;"   ::: "memory");

    // ---- output identity: lanes s<2 handle batch s, column jglob; q-even lanes push pairs ----
    const int ob    = s & 1;                  // batch for writer lanes (s<2)
    const int jglob = j0 + c0;
    const int jskew = jglob + ((jglob >> 6) << 1);
    const uint32_t loff0 = smem_u32(&h_s[0][ob*HROW + jskew]);   // buffer0; +HBUF*4 for buffer1
    uint32_t da[CLU], ma[CLU];
    #pragma unroll
    for (int r = 0; r < CLU; r++) {
        da[r] = mapa_u32(loff0, (uint32_t)r);
        ma[r] = mapa_u32(mbar0, (uint32_t)r);
    }
    const float* xp_ptr  = g_xp + (size_t)(cid*NB + ob)*Hq + jglob;
    float*       rnn_ptr = outbuf + RNN_OFF + (size_t)(cid*NB + ob)*Tq*Hq + jglob;

    for (int t = 0; t < Tq; t++) {
        const int cur = t & 1, nxt = cur ^ 1;
        if (t > 0) mbar_wait_parity(mbar0 + 8u*cur, (uint32_t)(((t - 1) >> 1) & 1));
        if (tid == 0 && t < Tq - 1) mbar_arrive_expect_tx(mbar0 + 8u*nxt, TXB);

        float xpv = 0.f;
        if (s < 2) xpv = __ldcg(xp_ptr + (size_t)t*(Bq*Hq));

        // ---- GEMV: 1 col x 2 batches over 64 k, packed FFMA2, broadcast LDS ----
        const float* hb = &h_s[cur][s*66];
        u64 a0 = 0ull, a1 = 0ull;
        #pragma unroll
        for (int m = 0; m < 32; m++) {
            u64 h0 = *(const u64*)&hb[2*m];
            u64 h1 = *(const u64*)&hb[HROW + 2*m];
            a0 = ffma2(h0, Wp[m], a0);
            a1 = ffma2(h1, Wp[m], a1);
        }
        // ---- butterfly reduce across 8 segments (lane bits 2..4) ----
        float f0 = hsum2(a0), f1 = hsum2(a1);
        #pragma unroll
        for (int off = 4; off <= 16; off <<= 1) {
            f0 += __shfl_xor_sync(0xffffffffu, f0, off);
            f1 += __shfl_xor_sync(0xffffffffu, f1, off);
        }
        float v  = (ob ? f1 : f0) + xpv;
        float hv = 1.f / (1.f + __expf(-v));
        float hv2 = __shfl_down_sync(0xffffffffu, hv, 1);   // col pair partner

        if (s < 2) {
            if ((q & 1) == 0) {                              // pair writer (cols jglob, jglob+1)
                *(float2*)(rnn_ptr + (size_t)t*Hq) = make_float2(hv, hv2);
                if (t == Tq - 1) {
                    *(float2*)(outbuf + HN_OFF + (size_t)(cid*NB + ob)*Hq + jglob) =
                        make_float2(hv, hv2);
                } else {
                    const u64 pk = packf2(hv, hv2);
                    const uint32_t doff = (uint32_t)(nxt * (HBUF*4));
                    const uint32_t moff = (uint32_t)(nxt * 8);
                    #pragma unroll
                    for (int r = 0; r < CLU; r++)
                        st_async_b64(da[r] + doff, pk, ma[r] + moff);
                }
            }
        }
    }
}

// ---------------- fc1: hidden = relu(rnn_out @ fc1_w + b1), 64x64 tiles, u64 FFMA2 ----------------
__global__ void __launch_bounds__(256) fc1_kernel(const float* __restrict__ A,   // [32768, 512]
                                                  const float* __restrict__ W,   // [512, 512]
                                                  const float* __restrict__ bias) {
    __shared__ __align__(16) float  As[64*32];     // [r][k] 8KB
    __shared__ __align__(16) float2 Ws2[16*64];    // [kk][c] = (W[2kk][c], W[2kk+1][c]) 8KB
    const int tid = threadIdx.x;      // 256
    const int bx = blockIdx.x;        // 8 col tiles
    const int by = blockIdx.y;        // 512 row tiles
    const int tx = tid & 15, ty = tid >> 4;
    const int row0 = by*64, col0 = bx*64;

    u64 acc[4][4];
    #pragma unroll
    for (int i = 0; i < 4; i++)
        #pragma unroll
        for (int j = 0; j < 4; j++) acc[i][j] = 0ull;

    for (int kt = 0; kt < Hq; kt += 32) {
        {
            int r = tid >> 3, kq = (tid & 7) << 2;
            *(float4*)&As[r*32 + kq]      = *(const float4*)&A[(size_t)(row0 + r)*Hq + kt + kq];
            *(float4*)&As[(r+32)*32 + kq] = *(const float4*)&A[(size_t)(row0 + r + 32)*Hq + kt + kq];
            #pragma unroll
            for (int i = 0; i < 4; i++) {
                int u = tid + i*256;
                int kk = u >> 6, c = u & 63;
                const float* wp = &W[(size_t)(kt + 2*kk)*Hq + col0 + c];
                Ws2[kk*64 + c] = make_float2(wp[0], wp[Hq]);
            }
        }
        __syncthreads();
        #pragma unroll
        for (int kk = 0; kk < 16; kk++) {
            ulonglong2 wa = *(const ulonglong2*)&Ws2[kk*64 + tx*4];
            ulonglong2 wb = *(const ulonglong2*)&Ws2[kk*64 + tx*4 + 2];
            #pragma unroll
            for (int r4 = 0; r4 < 4; r4++) {
                u64 a2 = *(const u64*)&As[(ty*4 + r4)*32 + 2*kk];
                acc[r4][0] = ffma2(a2, wa.x, acc[r4][0]);
                acc[r4][1] = ffma2(a2, wa.y, acc[r4][1]);
                acc[r4][2] = ffma2(a2, wb.x, acc[r4][2]);
                acc[r4][3] = ffma2(a2, wb.y, acc[r4][3]);
            }
        }
        __syncthreads();
    }

    float4 bv = *(const float4*)&bias[col0 + tx*4];
    #pragma unroll
    for (int i = 0; i < 4; i++) {
        float4 o;
        o.x = fmaxf(hsum2(acc[i][0]) + bv.x, 0.f);
        o.y = fmaxf(hsum2(acc[i][1]) + bv.y, 0.f);
        o.z = fmaxf(hsum2(acc[i][2]) + bv.z, 0.f);
        o.w = fmaxf(hsum2(acc[i][3]) + bv.w, 0.f);
        *(float4*)&g_hidden[(size_t)(row0 + ty*4 + i)*Hq + col0 + tx*4] = o;
    }
}

// ---------------- fc2: out = sigmoid(hidden @ fc2_w + b2), u64 FFMA2, 4 chains ----------------
__global__ void __launch_bounds__(256) fc2_kernel(const float* __restrict__ w2,   // [512, 16]
                                                  const float* __restrict__ b2,
                                                  float* __restrict__ out) {
    __shared__ __align__(16) float2 w2s[256*16];   // [kk][a] = (w2[2kk][a], w2[2kk+1][a]) 32KB
    const int tid = threadIdx.x;   // 256
    for (int e = tid; e < 256*16; e += 256) {
        int kk = e >> 4, a = e & 15;
        w2s[e] = make_float2(w2[(2*kk)*Aq + a], w2[(2*kk+1)*Aq + a]);
    }
    __syncthreads();

    const int r = tid >> 4;
    const int a = tid & 15;
    const size_t row = (size_t)blockIdx.x * 16 + r;
    const ulonglong2* hp = (const ulonglong2*)&g_hidden[row*Hq];

    u64 acc0 = 0ull, acc1 = 0ull, acc2 = 0ull, acc3 = 0ull;
    #pragma unroll 4
    for (int p = 0; p < 256; p += 4) {            // k-pairs
        ulonglong2 ha = hp[(p >> 1)];
        ulonglong2 hb = hp[(p >> 1) + 1];
        acc0 = ffma2(ha.x, *(const u64*)&w2s[(p+0)*16 + a], acc0);
        acc1 = ffma2(ha.y, *(const u64*)&w2s[(p+1)*16 + a], acc1);
        acc2 = ffma2(hb.x, *(const u64*)&w2s[(p+2)*16 + a], acc2);
        acc3 = ffma2(hb.y, *(const u64*)&w2s[(p+3)*16 + a], acc3);
    }
    float v = (hsum2(acc0) + hsum2(acc1)) + (hsum2(acc2) + hsum2(acc3)) + b2[a];
    out[row*Aq + a] = 1.f / (1.f + __expf(-v));
}

extern "C" void kernel_launch(void* const* d_in, const int* in_sizes, int n_in,
                              void* d_out, int out_size) {
    const float* inp  = (const float*)d_in[0];
    const float* hn   = (const float*)d_in[1];
    const float* w_hh = (const float*)d_in[2];
    const float* w_ih = (const float*)d_in[3];
    const float* fc1w = (const float*)d_in[4];
    const float* fc1b = (const float*)d_in[5];
    const float* fc2w = (const float*)d_in[6];
    const float* fc2b = (const float*)d_in[7];
    float* out = (float*)d_out;

    xp_kernel<<<dim3(32, 32), 512>>>(inp, w_ih);
    rnn_kernel<<<NCL*CLU, 512>>>(hn, w_hh, out);
    fc1_kernel<<<dim3(8, 512), 256>>>(out + RNN_OFF, fc1w, fc1b);
    fc2_kernel<<<(Bq*Tq)/16, 256>>>(fc2w, fc2b, out);
}

// round 6
// speedup vs baseline: 1.3008x; 1.3008x over previous
#include <cuda_runtime.h>
#include <cstdint>

#define Bq 32
#define Tq 1024
#define Iq 64
#define Hq 512
#define Aq 16

#define OUT_N  (Bq*Tq*Aq)          // 524288
#define HN_N   (Bq*Hq)             // 16384
#define HN_OFF OUT_N
#define RNN_OFF (OUT_N + HN_N)     // 540672

#define CLU 8                      // CTAs per cluster
#define NCL 16                     // clusters (16*8 = 128 CTAs)
#define NB  2                      // batches per cluster
#define TXB 4096                   // bytes per mbarrier phase: 8 CTAs * 128 vals * 4B

typedef unsigned long long u64;

// ---- scratch (static device globals: allocation-free) ----
__device__ float g_xp[Tq*Bq*Hq];               // x_proj [t][b][j]   (64 MB)
__device__ float g_hidden[(size_t)Bq*Tq*Hq];   // fc1 output (64 MB)

// ================= helpers =================
__device__ __forceinline__ uint32_t smem_u32(const void* p) {
    uint32_t a;
    asm("{ .reg .u64 t; cvta.to.shared.u64 t, %1; cvt.u32.u64 %0, t; }" : "=r"(a) : "l"(p));
    return a;
}
__device__ __forceinline__ uint32_t mapa_u32(uint32_t laddr, uint32_t rank) {
    uint32_t r;
    asm("mapa.shared::cluster.u32 %0, %1, %2;" : "=r"(r) : "r"(laddr), "r"(rank));
    return r;
}
__device__ __forceinline__ void st_async_f32(uint32_t raddr, float v, uint32_t rmbar) {
    asm volatile("st.async.shared::cluster.mbarrier::complete_tx::bytes.b32 [%0], %1, [%2];"
                 :: "r"(raddr), "f"(v), "r"(rmbar) : "memory");
}
__device__ __forceinline__ void mbar_init(uint32_t mbar, uint32_t cnt) {
    asm volatile("mbarrier.init.shared.b64 [%0], %1;" :: "r"(mbar), "r"(cnt) : "memory");
}
__device__ __forceinline__ void mbar_arrive_expect_tx(uint32_t mbar, uint32_t tx) {
    asm volatile("mbarrier.arrive.expect_tx.shared.b64 _, [%0], %1;" :: "r"(mbar), "r"(tx) : "memory");
}
__device__ __forceinline__ void mbar_wait_parity(uint32_t mbar, uint32_t parity) {
    asm volatile(
        "{\n\t"
        ".reg .pred P1;\n\t"
        "WAIT_LOOP_%=:\n\t"
        "mbarrier.try_wait.parity.acquire.cta.shared::cta.b64 P1, [%0], %1, 0x989680;\n\t"
        "@P1 bra.uni WAIT_DONE_%=;\n\t"
        "bra.uni WAIT_LOOP_%=;\n\t"
        "WAIT_DONE_%=:\n\t"
        "}" :: "r"(mbar), "r"(parity) : "memory");
}
// packed f32x2 on 64-bit carriers: no per-call repacking movs
__device__ __forceinline__ u64 ffma2(u64 a, u64 b, u64 c) {
    u64 d;
    asm("fma.rn.f32x2 %0, %1, %2, %3;" : "=l"(d) : "l"(a), "l"(b), "l"(c));
    return d;
}
__device__ __forceinline__ u64 packf2(float x, float y) {
    u64 r; asm("mov.b64 %0, {%1,%2};" : "=l"(r) : "f"(x), "f"(y)); return r;
}
__device__ __forceinline__ float2 unpackf2(u64 v) {
    float2 f; asm("mov.b64 {%0,%1}, %2;" : "=f"(f.x), "=f"(f.y) : "l"(v)); return f;
}
__device__ __forceinline__ float hsum2(u64 v) { float2 f = unpackf2(v); return f.x + f.y; }

// ---------------- x_proj: xp[t][b][j] = sum_i inp[b][t][i] * w_ih[i][j] ----------------
__global__ void xp_kernel(const float* __restrict__ inp, const float* __restrict__ w_ih) {
    const int b   = blockIdx.x;   // 32
    const int tc  = blockIdx.y;   // 32 chunks of 32 timesteps
    const int tid = threadIdx.x;  // 512 (j)
    __shared__ float s_in[32*64];
    const float* src = inp + (size_t)b*Tq*Iq + (size_t)tc*32*Iq;
    ((float4*)s_in)[tid] = ((const float4*)src)[tid];
    __syncthreads();

    float acc[32];
    #pragma unroll
    for (int tt = 0; tt < 32; tt++) acc[tt] = 0.f;

    #pragma unroll 8
    for (int i = 0; i < Iq; i++) {
        float w = w_ih[i*Hq + tid];
        #pragma unroll
        for (int tt = 0; tt < 32; tt++)
            acc[tt] = fmaf(s_in[tt*64 + i], w, acc[tt]);
    }
    #pragma unroll
    for (int tt = 0; tt < 32; tt++)
        g_xp[(size_t)(tc*32 + tt)*(Bq*Hq) + b*Hq + tid] = acc[tt];
}

// ---------------- RNN scan: 16 independent clusters of 8 CTAs (R3 skeleton) ----------------
// Cluster c handles batches {2c, 2c+1}. CTA rank r owns output columns [r*64, r*64+64).
// Weights in registers as u64 k-pairs. h exchanged via st.async + mbarrier (double buffered).
// Reduce via psum SMEM + __syncthreads (the empirically fastest schedule).
__global__ void __launch_bounds__(256, 1) __cluster_dims__(CLU, 1, 1)
rnn_kernel(const float* __restrict__ hn, const float* __restrict__ w_hh,
           float* __restrict__ outbuf) {
    __shared__ __align__(16) float  h_s[2][NB*Hq];     // [buf][b*512 + k]  8KB
    __shared__ __align__(16) float2 psum[NB][512];     // [b][s*64 + col]   8KB
    __shared__ __align__(8)  unsigned long long mbar_s[2];

    const int tid = threadIdx.x;
    uint32_t rank;
    asm("mov.u32 %0, %%cluster_ctarank;" : "=r"(rank));
    const int cid = blockIdx.x >> 3;        // cluster id 0..15
    const int j0  = (int)rank * 64;         // column slice base
    const int s   = tid >> 5;               // k-segment 0..7 (one warp each)
    const int jl  = tid & 31;               // column pair index 0..31
    const int kb  = s * 64;

    // ---- stationary W slice as u64 k-pairs ----
    u64 Wc0[32], Wc1[32];
    {
        const float* wbase = w_hh + (size_t)kb*Hq + j0 + jl*2;
        #pragma unroll
        for (int m = 0; m < 32; m++) {
            const float* wp = wbase + (size_t)(2*m)*Hq;
            Wc0[m] = packf2(wp[0], wp[Hq]);
            Wc1[m] = packf2(wp[1], wp[Hq + 1]);
        }
    }
    // ---- h0 into buffer 0 ----
    for (int e = tid; e < NB*Hq; e += 256) {
        int b = e >> 9, k = e & 511;
        h_s[0][e] = hn[(size_t)(cid*NB + b)*Hq + k];
    }
    const uint32_t mbar0 = smem_u32(&mbar_s[0]);
    if (tid == 0) { mbar_init(mbar0, 1); mbar_init(mbar0 + 8, 1); }
    __syncthreads();
    asm volatile("barrier.cluster.arrive.aligned;" ::: "memory");
    asm volatile("barrier.cluster.wait.aligned;"   ::: "memory");

    const int fb = tid >> 6;                 // finisher batch (tid<128)
    const int fc = tid & 63;                 // finisher column (local)
    const uint32_t h_push_base = smem_u32(&h_s[0][0]);

    for (int t = 0; t < Tq; t++) {
        const int cur = t & 1, nxt = cur ^ 1;
        if (t > 0) mbar_wait_parity(mbar0 + 8u*cur, (uint32_t)(((t - 1) >> 1) & 1));
        if (tid == 0 && t < Tq - 1) mbar_arrive_expect_tx(mbar0 + 8u*nxt, TXB);

        // prefetch xp for the finisher phase (in flight during compute)
        float xpv = 0.f;
        if (tid < 128)
            xpv = __ldcg(&g_xp[(size_t)t*(Bq*Hq) + (cid*NB + fb)*Hq + j0 + fc]);

        // ---- main GEMV: 2 batches x 2 cols, u64 packed FFMA2 (no repack movs) ----
        const float* hb0 = &h_s[cur][0];
        const float* hb1 = &h_s[cur][Hq];
        u64 a00 = 0ull, a01 = 0ull, a10 = 0ull, a11 = 0ull;
        #pragma unroll
        for (int m = 0; m < 32; m++) {
            u64 h0 = *(const u64*)&hb0[kb + 2*m];   // broadcast LDS.64
            u64 h1 = *(const u64*)&hb1[kb + 2*m];
            a00 = ffma2(h0, Wc0[m], a00);
            a01 = ffma2(h0, Wc1[m], a01);
            a10 = ffma2(h1, Wc0[m], a10);
            a11 = ffma2(h1, Wc1[m], a11);
        }
        {
            float2 p00 = unpackf2(a00), p01 = unpackf2(a01);
            float2 p10 = unpackf2(a10), p11 = unpackf2(a11);
            *(float4*)&psum[0][kb + jl*2] = make_float4(p00.x, p00.y, p01.x, p01.y);
            *(float4*)&psum[1][kb + jl*2] = make_float4(p10.x, p10.y, p11.x, p11.y);
        }
        __syncthreads();

        // ---- finish: reduce 8 segments, sigmoid, store, push to peers ----
        if (tid < 128) {
            float2 acc = psum[fb][fc];
            #pragma unroll
            for (int s2 = 1; s2 < 8; s2++) {
                float2 p = psum[fb][s2*64 + fc];
                acc.x += p.x; acc.y += p.y;
            }
            float v  = acc.x + acc.y + xpv;
            float hv = 1.f / (1.f + __expf(-v));
            const size_t bglob = (size_t)(cid*NB + fb);
            outbuf[RNN_OFF + bglob*Tq*Hq + (size_t)t*Hq + j0 + fc] = hv;
            if (t == Tq - 1) {
                outbuf[HN_OFF + bglob*Hq + j0 + fc] = hv;
            } else {
                uint32_t loff = h_push_base + (uint32_t)((nxt*NB*Hq + fb*Hq + j0 + fc) * 4);
                uint32_t lmb  = mbar0 + 8u*nxt;
                #pragma unroll
                for (uint32_t r = 0; r < CLU; r++)
                    st_async_f32(mapa_u32(loff, r), hv, mapa_u32(lmb, r));
            }
        }
        __syncthreads();   // psum reuse + uniform re-entry
    }
}

// ---------------- fc1: hidden = relu(rnn_out @ fc1_w + b1), 64x64 tiles, u64 FFMA2 ----------------
__global__ void __launch_bounds__(256) fc1_kernel(const float* __restrict__ A,   // [32768, 512]
                                                  const float* __restrict__ W,   // [512, 512]
                                                  const float* __restrict__ bias) {
    __shared__ __align__(16) float  As[64*32];     // [r][k] 8KB
    __shared__ __align__(16) float2 Ws2[16*64];    // [kk][c] = (W[2kk][c], W[2kk+1][c]) 8KB
    const int tid = threadIdx.x;      // 256
    const int bx = blockIdx.x;        // 8 col tiles
    const int by = blockIdx.y;        // 512 row tiles
    const int tx = tid & 15, ty = tid >> 4;
    const int row0 = by*64, col0 = bx*64;

    u64 acc[4][4];
    #pragma unroll
    for (int i = 0; i < 4; i++)
        #pragma unroll
        for (int j = 0; j < 4; j++) acc[i][j] = 0ull;

    for (int kt = 0; kt < Hq; kt += 32) {
        {
            int r = tid >> 3, kq = (tid & 7) << 2;
            *(float4*)&As[r*32 + kq]      = *(const float4*)&A[(size_t)(row0 + r)*Hq + kt + kq];
            *(float4*)&As[(r+32)*32 + kq] = *(const float4*)&A[(size_t)(row0 + r + 32)*Hq + kt + kq];
            #pragma unroll
            for (int i = 0; i < 4; i++) {
                int u = tid + i*256;
                int kk = u >> 6, c = u & 63;
                const float* wp = &W[(size_t)(kt + 2*kk)*Hq + col0 + c];
                Ws2[kk*64 + c] = make_float2(wp[0], wp[Hq]);
            }
        }
        __syncthreads();
        #pragma unroll
        for (int kk = 0; kk < 16; kk++) {
            ulonglong2 wa = *(const ulonglong2*)&Ws2[kk*64 + tx*4];
            ulonglong2 wb = *(const ulonglong2*)&Ws2[kk*64 + tx*4 + 2];
            #pragma unroll
            for (int r4 = 0; r4 < 4; r4++) {
                u64 a2 = *(const u64*)&As[(ty*4 + r4)*32 + 2*kk];
                acc[r4][0] = ffma2(a2, wa.x, acc[r4][0]);
                acc[r4][1] = ffma2(a2, wa.y, acc[r4][1]);
                acc[r4][2] = ffma2(a2, wb.x, acc[r4][2]);
                acc[r4][3] = ffma2(a2, wb.y, acc[r4][3]);
            }
        }
        __syncthreads();
    }

    float4 bv = *(const float4*)&bias[col0 + tx*4];
    #pragma unroll
    for (int i = 0; i < 4; i++) {
        float4 o;
        o.x = fmaxf(hsum2(acc[i][0]) + bv.x, 0.f);
        o.y = fmaxf(hsum2(acc[i][1]) + bv.y, 0.f);
        o.z = fmaxf(hsum2(acc[i][2]) + bv.z, 0.f);
        o.w = fmaxf(hsum2(acc[i][3]) + bv.w, 0.f);
        *(float4*)&g_hidden[(size_t)(row0 + ty*4 + i)*Hq + col0 + tx*4] = o;
    }
}

// ---------------- fc2: out = sigmoid(hidden @ fc2_w + b2)  (R3-measured-best version) ----------------
__global__ void fc2_kernel(const float* __restrict__ w2,   // [512, 16]
                           const float* __restrict__ b2,
                           float* __restrict__ out) {
    __shared__ float w2s[Hq*Aq];   // 32 KB
    const int tid = threadIdx.x;   // 256
    for (int e = tid; e < Hq*Aq; e += 256) w2s[e] = w2[e];
    __syncthreads();

    const int r = tid >> 4;        // 16 rows per block
    const int a = tid & 15;
    const size_t row = (size_t)blockIdx.x * 16 + r;
    const float* hrow = &g_hidden[row*Hq];

    float acc = 0.f;
    #pragma unroll 8
    for (int k = 0; k < Hq; k += 4) {
        float4 hv = *(const float4*)&hrow[k];
        acc = fmaf(hv.x, w2s[(k+0)*Aq + a], acc);
        acc = fmaf(hv.y, w2s[(k+1)*Aq + a], acc);
        acc = fmaf(hv.z, w2s[(k+2)*Aq + a], acc);
        acc = fmaf(hv.w, w2s[(k+3)*Aq + a], acc);
    }
    float v = acc + b2[a];
    out[row*Aq + a] = 1.f / (1.f + __expf(-v));
}

extern "C" void kernel_launch(void* const* d_in, const int* in_sizes, int n_in,
                              void* d_out, int out_size) {
    const float* inp  = (const float*)d_in[0];
    const float* hn   = (const float*)d_in[1];
    const float* w_hh = (const float*)d_in[2];
    const float* w_ih = (const float*)d_in[3];
    const float* fc1w = (const float*)d_in[4];
    const float* fc1b = (const float*)d_in[5];
    const float* fc2w = (const float*)d_in[6];
    const float* fc2b = (const float*)d_in[7];
    float* out = (float*)d_out;

    xp_kernel<<<dim3(32, 32), 512>>>(inp, w_ih);
    rnn_kernel<<<NCL*CLU, 256>>>(hn, w_hh, out);
    fc1_kernel<<<dim3(8, 512), 256>>>(out + RNN_OFF, fc1w, fc1b);
    fc2_kernel<<<(Bq*Tq)/16, 256>>>(fc2w, fc2b, out);
}

// round 7
// speedup vs baseline: 1.3407x; 1.0306x over previous
#include <cuda_runtime.h>
#include <cstdint>

#define Bq 32
#define Tq 1024
#define Iq 64
#define Hq 512
#define Aq 16

#define OUT_N  (Bq*Tq*Aq)          // 524288
#define HN_N   (Bq*Hq)             // 16384
#define HN_OFF OUT_N
#define RNN_OFF (OUT_N + HN_N)     // 540672

#define CLU 8                      // CTAs per cluster
#define NCL 16                     // clusters (16*8 = 128 CTAs)
#define NB  2                      // batches per cluster
#define CHUNK_B 512                // bytes per source chunk: 2 batches * 64 cols * 4B
#define HSTRIDE (CLU*NB*64*4)      // bytes per h buffer (4096)

typedef unsigned long long u64;

// ---- scratch (static device globals: allocation-free) ----
__device__ float g_xp[Tq*Bq*Hq];               // x_proj [t][b][j]   (64 MB)
__device__ float g_hidden[(size_t)Bq*Tq*Hq];   // fc1 output (64 MB)

// ================= helpers =================
__device__ __forceinline__ uint32_t smem_u32(const void* p) {
    uint32_t a;
    asm("{ .reg .u64 t; cvta.to.shared.u64 t, %1; cvt.u32.u64 %0, t; }" : "=r"(a) : "l"(p));
    return a;
}
__device__ __forceinline__ uint32_t mapa_u32(uint32_t laddr, uint32_t rank) {
    uint32_t r;
    asm("mapa.shared::cluster.u32 %0, %1, %2;" : "=r"(r) : "r"(laddr), "r"(rank));
    return r;
}
__device__ __forceinline__ void mbar_init(uint32_t mbar, uint32_t cnt) {
    asm volatile("mbarrier.init.shared.b64 [%0], %1;" :: "r"(mbar), "r"(cnt) : "memory");
}
__device__ __forceinline__ void mbar_arrive_expect_tx(uint32_t mbar, uint32_t tx) {
    asm volatile("mbarrier.arrive.expect_tx.shared.b64 _, [%0], %1;" :: "r"(mbar), "r"(tx) : "memory");
}
__device__ __forceinline__ void mbar_wait_parity(uint32_t mbar, uint32_t parity) {
    asm volatile(
        "{\n\t"
        ".reg .pred P1;\n\t"
        "WAIT_LOOP_%=:\n\t"
        "mbarrier.try_wait.parity.acquire.cta.shared::cta.b64 P1, [%0], %1, 0x989680;\n\t"
        "@P1 bra.uni WAIT_DONE_%=;\n\t"
        "bra.uni WAIT_LOOP_%=;\n\t"
        "WAIT_DONE_%=:\n\t"
        "}" :: "r"(mbar), "r"(parity) : "memory");
}
// bulk SMEM->peer-SMEM copy, completion accounted on the PEER's mbarrier
__device__ __forceinline__ void bulk_copy_to_peer(uint32_t dst_cluster, uint32_t src_cta,
                                                  uint32_t bytes, uint32_t rmbar_cluster) {
    asm volatile(
        "cp.async.bulk.shared::cluster.shared::cta.mbarrier::complete_tx::bytes [%0], [%1], %2, [%3];"
        :: "r"(dst_cluster), "r"(src_cta), "r"(bytes), "r"(rmbar_cluster) : "memory");
}
__device__ __forceinline__ void fence_proxy_async_cta() {
    asm volatile("fence.proxy.async.shared::cta;" ::: "memory");
}
// packed f32x2 on 64-bit carriers
__device__ __forceinline__ u64 ffma2(u64 a, u64 b, u64 c) {
    u64 d;
    asm("fma.rn.f32x2 %0, %1, %2, %3;" : "=l"(d) : "l"(a), "l"(b), "l"(c));
    return d;
}
__device__ __forceinline__ u64 packf2(float x, float y) {
    u64 r; asm("mov.b64 %0, {%1,%2};" : "=l"(r) : "f"(x), "f"(y)); return r;
}
__device__ __forceinline__ float2 unpackf2(u64 v) {
    float2 f; asm("mov.b64 {%0,%1}, %2;" : "=f"(f.x), "=f"(f.y) : "l"(v)); return f;
}
__device__ __forceinline__ float hsum2(u64 v) { float2 f = unpackf2(v); return f.x + f.y; }

// ---------------- x_proj ----------------
__global__ void xp_kernel(const float* __restrict__ inp, const float* __restrict__ w_ih) {
    const int b   = blockIdx.x;
    const int tc  = blockIdx.y;
    const int tid = threadIdx.x;  // 512
    __shared__ float s_in[32*64];
    const float* src = inp + (size_t)b*Tq*Iq + (size_t)tc*32*Iq;
    ((float4*)s_in)[tid] = ((const float4*)src)[tid];
    __syncthreads();

    float acc[32];
    #pragma unroll
    for (int tt = 0; tt < 32; tt++) acc[tt] = 0.f;
    #pragma unroll 8
    for (int i = 0; i < Iq; i++) {
        float w = w_ih[i*Hq + tid];
        #pragma unroll
        for (int tt = 0; tt < 32; tt++)
            acc[tt] = fmaf(s_in[tt*64 + i], w, acc[tt]);
    }
    #pragma unroll
    for (int tt = 0; tt < 32; tt++)
        g_xp[(size_t)(tc*32 + tt)*(Bq*Hq) + b*Hq + tid] = acc[tt];
}

// ---------------- RNN scan: chunked h + per-source mbarriers + bulk DSMEM pushes ----------------
// h_s[buf][c][b][64]: chunk c = columns/k-range [64c,64c+64) produced by CTA rank c.
// Warp s computes k-segment s and waits ONLY on chunk s's barrier (none if s==rank).
// Finish: psum reduce -> sigmoid -> STG rnn_out, STS stage + own chunk; then 7 threads each
// issue ONE 512B bulk copy to one peer (replaces 1024 st.async messages).
__global__ void __launch_bounds__(256, 1) __cluster_dims__(CLU, 1, 1)
rnn_kernel(const float* __restrict__ hn, const float* __restrict__ w_hh,
           float* __restrict__ outbuf) {
    __shared__ __align__(16) float  h_s[2][CLU][NB][64];   // 8KB
    __shared__ __align__(16) float  stage[2][NB*64];       // 1KB outbound staging
    __shared__ __align__(16) float2 psum[NB][512];         // 8KB
    __shared__ __align__(8)  unsigned long long mbar_s[2][CLU];

    const int tid = threadIdx.x;
    uint32_t rank;
    asm("mov.u32 %0, %%cluster_ctarank;" : "=r"(rank));
    const int cid = blockIdx.x >> 3;
    const int j0  = (int)rank * 64;
    const int s   = tid >> 5;               // k-segment / source chunk (one warp each)
    const int jl  = tid & 31;
    const int kb  = s * 64;

    // ---- stationary W slice as u64 k-pairs ----
    u64 Wc0[32], Wc1[32];
    {
        const float* wbase = w_hh + (size_t)kb*Hq + j0 + jl*2;
        #pragma unroll
        for (int m = 0; m < 32; m++) {
            const float* wp = wbase + (size_t)(2*m)*Hq;
            Wc0[m] = packf2(wp[0], wp[Hq]);
            Wc1[m] = packf2(wp[1], wp[Hq + 1]);
        }
    }
    // ---- h0 into buffer 0 (chunked layout) ----
    for (int e = tid; e < NB*Hq; e += 256) {
        int b = e >> 9, k = e & 511;
        h_s[0][k >> 6][b][k & 63] = hn[(size_t)(cid*NB + b)*Hq + k];
    }
    const uint32_t mbar0  = smem_u32(&mbar_s[0][0]);
    const uint32_t hbase  = smem_u32(&h_s[0][0][0][0]);
    const uint32_t sbase  = smem_u32(&stage[0][0]);
    if (tid == 0) {
        #pragma unroll
        for (int i = 0; i < 2*CLU; i++) mbar_init(mbar0 + 8u*i, 1);
    }
    __syncthreads();
    asm volatile("barrier.cluster.arrive.aligned;" ::: "memory");
    asm volatile("barrier.cluster.wait.aligned;"   ::: "memory");

    const int fb = tid >> 6;                 // finisher batch (tid<128)
    const int fc = tid & 63;                 // finisher column (local)
    // per-peer remote addresses (tid<8 = peer index); own chunk region on each peer
    uint32_t dst_p = 0, mb_p = 0;
    if (tid < CLU) {
        dst_p = mapa_u32(hbase + (uint32_t)rank * CHUNK_B, (uint32_t)tid);
        mb_p  = mapa_u32(mbar0 + 8u*rank, (uint32_t)tid);
    }
    const bool is_pusher = (tid < CLU) && (tid != (int)rank);

    for (int t = 0; t < Tq; t++) {
        const int cur = t & 1, nxt = cur ^ 1;
        // post expects for NEXT step's arrivals (barrier set nxt), one thread per source chunk
        if (t < Tq - 1 && tid < CLU && tid != (int)rank)
            mbar_arrive_expect_tx(mbar0 + 8u*(nxt*CLU + tid), CHUNK_B);

        // prefetch xp for the finisher phase
        float xpv = 0.f;
        if (tid < 128)
            xpv = __ldcg(&g_xp[(size_t)t*(Bq*Hq) + (cid*NB + fb)*Hq + j0 + fc]);

        // wait only for THIS warp's source chunk (own chunk written locally last step)
        if (t > 0 && s != (int)rank) {
            const uint32_t par = (uint32_t)(((t >> 1) - ((t & 1) ^ 1)) & 1);
            mbar_wait_parity(mbar0 + 8u*(cur*CLU + s), par);
        }

        // ---- GEMV: 2 batches x 2 cols over this warp's 64-k chunk ----
        const float* hb0 = &h_s[cur][s][0][0];
        const float* hb1 = &h_s[cur][s][1][0];
        u64 a00 = 0ull, a01 = 0ull, a10 = 0ull, a11 = 0ull;
        #pragma unroll
        for (int m = 0; m < 32; m++) {
            u64 h0 = *(const u64*)&hb0[2*m];   // broadcast LDS.64
            u64 h1 = *(const u64*)&hb1[2*m];
            a00 = ffma2(h0, Wc0[m], a00);
            a01 = ffma2(h0, Wc1[m], a01);
            a10 = ffma2(h1, Wc0[m], a10);
            a11 = ffma2(h1, Wc1[m], a11);
        }
        {
            float2 p00 = unpackf2(a00), p01 = unpackf2(a01);
            float2 p10 = unpackf2(a10), p11 = unpackf2(a11);
            *(float4*)&psum[0][kb + jl*2] = make_float4(p00.x, p00.y, p01.x, p01.y);
            *(float4*)&psum[1][kb + jl*2] = make_float4(p10.x, p10.y, p11.x, p11.y);
        }
        __syncthreads();

        // ---- finish: reduce 8 segments, sigmoid, store, stage outbound ----
        if (tid < 128) {
            float2 acc = psum[fb][fc];
            #pragma unroll
            for (int s2 = 1; s2 < 8; s2++) {
                float2 p = psum[fb][s2*64 + fc];
                acc.x += p.x; acc.y += p.y;
            }
            float v  = acc.x + acc.y + xpv;
            float hv = 1.f / (1.f + __expf(-v));
            const size_t bglob = (size_t)(cid*NB + fb);
            outbuf[RNN_OFF + bglob*Tq*Hq + (size_t)t*Hq + j0 + fc] = hv;
            if (t == Tq - 1) {
                outbuf[HN_OFF + bglob*Hq + j0 + fc] = hv;
            } else {
                stage[nxt][fb*64 + fc] = hv;            // outbound
                h_s[nxt][rank][fb][fc] = hv;            // own chunk, local
            }
        }
        __syncthreads();   // psum reuse + stage/own-chunk visibility

        // ---- one 512B bulk copy per peer (7 threads issue in parallel) ----
        if (t < Tq - 1 && is_pusher) {
            fence_proxy_async_cta();
            bulk_copy_to_peer(dst_p + (uint32_t)(nxt * HSTRIDE),
                              sbase + (uint32_t)(nxt * CHUNK_B),
                              CHUNK_B,
                              mb_p + (uint32_t)(nxt * (CLU*8)));
        }
    }
}

// ---------------- fc1: hidden = relu(rnn_out @ fc1_w + b1), 64x64 tiles, u64 FFMA2 ----------------
__global__ void __launch_bounds__(256) fc1_kernel(const float* __restrict__ A,   // [32768, 512]
                                                  const float* __restrict__ W,   // [512, 512]
                                                  const float* __restrict__ bias) {
    __shared__ __align__(16) float  As[64*32];
    __shared__ __align__(16) float2 Ws2[16*64];
    const int tid = threadIdx.x;      // 256
    const int bx = blockIdx.x;
    const int by = blockIdx.y;
    const int tx = tid & 15, ty = tid >> 4;
    const int row0 = by*64, col0 = bx*64;

    u64 acc[4][4];
    #pragma unroll
    for (int i = 0; i < 4; i++)
        #pragma unroll
        for (int j = 0; j < 4; j++) acc[i][j] = 0ull;

    for (int kt = 0; kt < Hq; kt += 32) {
        {
            int r = tid >> 3, kq = (tid & 7) << 2;
            *(float4*)&As[r*32 + kq]      = *(const float4*)&A[(size_t)(row0 + r)*Hq + kt + kq];
            *(float4*)&As[(r+32)*32 + kq] = *(const float4*)&A[(size_t)(row0 + r + 32)*Hq + kt + kq];
            #pragma unroll
            for (int i = 0; i < 4; i++) {
                int u = tid + i*256;
                int kk = u >> 6, c = u & 63;
                const float* wp = &W[(size_t)(kt + 2*kk)*Hq + col0 + c];
                Ws2[kk*64 + c] = make_float2(wp[0], wp[Hq]);
            }
        }
        __syncthreads();
        #pragma unroll
        for (int kk = 0; kk < 16; kk++) {
            ulonglong2 wa = *(const ulonglong2*)&Ws2[kk*64 + tx*4];
            ulonglong2 wb = *(const ulonglong2*)&Ws2[kk*64 + tx*4 + 2];
            #pragma unroll
            for (int r4 = 0; r4 < 4; r4++) {
                u64 a2 = *(const u64*)&As[(ty*4 + r4)*32 + 2*kk];
                acc[r4][0] = ffma2(a2, wa.x, acc[r4][0]);
                acc[r4][1] = ffma2(a2, wa.y, acc[r4][1]);
                acc[r4][2] = ffma2(a2, wb.x, acc[r4][2]);
                acc[r4][3] = ffma2(a2, wb.y, acc[r4][3]);
            }
        }
        __syncthreads();
    }

    float4 bv = *(const float4*)&bias[col0 + tx*4];
    #pragma unroll
    for (int i = 0; i < 4; i++) {
        float4 o;
        o.x = fmaxf(hsum2(acc[i][0]) + bv.x, 0.f);
        o.y = fmaxf(hsum2(acc[i][1]) + bv.y, 0.f);
        o.z = fmaxf(hsum2(acc[i][2]) + bv.z, 0.f);
        o.w = fmaxf(hsum2(acc[i][3]) + bv.w, 0.f);
        *(float4*)&g_hidden[(size_t)(row0 + ty*4 + i)*Hq + col0 + tx*4] = o;
    }
}

// ---------------- fc2 ----------------
__global__ void fc2_kernel(const float* __restrict__ w2,
                           const float* __restrict__ b2,
                           float* __restrict__ out) {
    __shared__ float w2s[Hq*Aq];
    const int tid = threadIdx.x;   // 256
    for (int e = tid; e < Hq*Aq; e += 256) w2s[e] = w2[e];
    __syncthreads();

    const int r = tid >> 4;
    const int a = tid & 15;
    const size_t row = (size_t)blockIdx.x * 16 + r;
    const float* hrow = &g_hidden[row*Hq];

    float acc = 0.f;
    #pragma unroll 8
    for (int k = 0; k < Hq; k += 4) {
        float4 hv = *(const float4*)&hrow[k];
        acc = fmaf(hv.x, w2s[(k+0)*Aq + a], acc);
        acc = fmaf(hv.y, w2s[(k+1)*Aq + a], acc);
        acc = fmaf(hv.z, w2s[(k+2)*Aq + a], acc);
        acc = fmaf(hv.w, w2s[(k+3)*Aq + a], acc);
    }
    float v = acc + b2[a];
    out[row*Aq + a] = 1.f / (1.f + __expf(-v));
}

extern "C" void kernel_launch(void* const* d_in, const int* in_sizes, int n_in,
                              void* d_out, int out_size) {
    const float* inp  = (const float*)d_in[0];
    const float* hn   = (const float*)d_in[1];
    const float* w_hh = (const float*)d_in[2];
    const float* w_ih = (const float*)d_in[3];
    const float* fc1w = (const float*)d_in[4];
    const float* fc1b = (const float*)d_in[5];
    const float* fc2w = (const float*)d_in[6];
    const float* fc2b = (const float*)d_in[7];
    float* out = (float*)d_out;

    xp_kernel<<<dim3(32, 32), 512>>>(inp, w_ih);
    rnn_kernel<<<NCL*CLU, 256>>>(hn, w_hh, out);
    fc1_kernel<<<dim3(8, 512), 256>>>(out + RNN_OFF, fc1w, fc1b);
    fc2_kernel<<<(Bq*Tq)/16, 256>>>(fc2w, fc2b, out);
}

// round 8
// speedup vs baseline: 1.6503x; 1.2309x over previous
#include <cuda_runtime.h>
#include <cstdint>

#define Bq 32
#define Tq 1024
#define Iq 64
#define Hq 512
#define Aq 16

#define OUT_N  (Bq*Tq*Aq)          // 524288
#define HN_N   (Bq*Hq)             // 16384
#define HN_OFF OUT_N
#define RNN_OFF (OUT_N + HN_N)     // 540672

#define CLU 8                      // CTAs per cluster
#define NCL 16                     // clusters (16*8 = 128 CTAs)
#define NB  2                      // batches per cluster
#define CHUNK_B 512                // bytes per source chunk: 2 batches * 64 cols * 4B
#define HSTRIDE (CLU*NB*64*4)      // bytes per h buffer (4096)

typedef unsigned long long u64;

// ---- scratch (static device globals: allocation-free) ----
__device__ float g_xp[Tq*Bq*Hq];               // x_proj [t][b][j]   (64 MB)
__device__ float g_hidden[(size_t)Bq*Tq*Hq];   // fc1 output (64 MB)

// ================= helpers =================
__device__ __forceinline__ uint32_t smem_u32(const void* p) {
    uint32_t a;
    asm("{ .reg .u64 t; cvta.to.shared.u64 t, %1; cvt.u32.u64 %0, t; }" : "=r"(a) : "l"(p));
    return a;
}
__device__ __forceinline__ uint32_t mapa_u32(uint32_t laddr, uint32_t rank) {
    uint32_t r;
    asm("mapa.shared::cluster.u32 %0, %1, %2;" : "=r"(r) : "r"(laddr), "r"(rank));
    return r;
}
__device__ __forceinline__ void mbar_init(uint32_t mbar, uint32_t cnt) {
    asm volatile("mbarrier.init.shared.b64 [%0], %1;" :: "r"(mbar), "r"(cnt) : "memory");
}
__device__ __forceinline__ void mbar_arrive_expect_tx(uint32_t mbar, uint32_t tx) {
    asm volatile("mbarrier.arrive.expect_tx.shared.b64 _, [%0], %1;" :: "r"(mbar), "r"(tx) : "memory");
}
__device__ __forceinline__ void mbar_wait_parity(uint32_t mbar, uint32_t parity) {
    asm volatile(
        "{\n\t"
        ".reg .pred P1;\n\t"
        "WAIT_LOOP_%=:\n\t"
        "mbarrier.try_wait.parity.acquire.cta.shared::cta.b64 P1, [%0], %1, 0x989680;\n\t"
        "@P1 bra.uni WAIT_DONE_%=;\n\t"
        "bra.uni WAIT_LOOP_%=;\n\t"
        "WAIT_DONE_%=:\n\t"
        "}" :: "r"(mbar), "r"(parity) : "memory");
}
// bulk SMEM->peer-SMEM copy, completion accounted on the PEER's mbarrier
__device__ __forceinline__ void bulk_copy_to_peer(uint32_t dst_cluster, uint32_t src_cta,
                                                  uint32_t bytes, uint32_t rmbar_cluster) {
    asm volatile(
        "cp.async.bulk.shared::cluster.shared::cta.mbarrier::complete_tx::bytes [%0], [%1], %2, [%3];"
        :: "r"(dst_cluster), "r"(src_cta), "r"(bytes), "r"(rmbar_cluster) : "memory");
}
__device__ __forceinline__ void fence_proxy_async_cta() {
    asm volatile("fence.proxy.async.shared::cta;" ::: "memory");
}
// packed f32x2 on 64-bit carriers
__device__ __forceinline__ u64 ffma2(u64 a, u64 b, u64 c) {
    u64 d;
    asm("fma.rn.f32x2 %0, %1, %2, %3;" : "=l"(d) : "l"(a), "l"(b), "l"(c));
    return d;
}
__device__ __forceinline__ u64 packf2(float x, float y) {
    u64 r; asm("mov.b64 %0, {%1,%2};" : "=l"(r) : "f"(x), "f"(y)); return r;
}
__device__ __forceinline__ float2 unpackf2(u64 v) {
    float2 f; asm("mov.b64 {%0,%1}, %2;" : "=f"(f.x), "=f"(f.y) : "l"(v)); return f;
}
__device__ __forceinline__ float hsum2(u64 v) { float2 f = unpackf2(v); return f.x + f.y; }

// ---------------- x_proj ----------------
__global__ void xp_kernel(const float* __restrict__ inp, const float* __restrict__ w_ih) {
    const int b   = blockIdx.x;
    const int tc  = blockIdx.y;
    const int tid = threadIdx.x;  // 512
    __shared__ float s_in[32*64];
    const float* src = inp + (size_t)b*Tq*Iq + (size_t)tc*32*Iq;
    ((float4*)s_in)[tid] = ((const float4*)src)[tid];
    __syncthreads();

    float acc[32];
    #pragma unroll
    for (int tt = 0; tt < 32; tt++) acc[tt] = 0.f;
    #pragma unroll 8
    for (int i = 0; i < Iq; i++) {
        float w = w_ih[i*Hq + tid];
        #pragma unroll
        for (int tt = 0; tt < 32; tt++)
            acc[tt] = fmaf(s_in[tt*64 + i], w, acc[tt]);
    }
    #pragma unroll
    for (int tt = 0; tt < 32; tt++)
        g_xp[(size_t)(tc*32 + tt)*(Bq*Hq) + b*Hq + tid] = acc[tt];
}

// ---------------- RNN scan (half-range launch): chunked h + per-source mbarriers + bulk pushes ----
// Runs steps [t0, t0+tlen). h seeded from h_init (row stride h_stride). The step-511 h state is
// recovered by launch 2 from rnn_out itself (already a required output).
__global__ void __launch_bounds__(256, 1) __cluster_dims__(CLU, 1, 1)
rnn_kernel(const float* __restrict__ h_init, size_t h_stride, int t0, int tlen,
           const float* __restrict__ w_hh, float* __restrict__ outbuf) {
    __shared__ __align__(16) float  h_s[2][CLU][NB][64];   // 8KB
    __shared__ __align__(16) float  stage[2][NB*64];       // 1KB outbound staging
    __shared__ __align__(16) float2 psum[NB][512];         // 8KB
    __shared__ __align__(8)  unsigned long long mbar_s[2][CLU];

    const int tid = threadIdx.x;
    uint32_t rank;
    asm("mov.u32 %0, %%cluster_ctarank;" : "=r"(rank));
    const int cid = blockIdx.x >> 3;
    const int j0  = (int)rank * 64;
    const int s   = tid >> 5;               // k-segment / source chunk (one warp each)
    const int jl  = tid & 31;
    const int kb  = s * 64;

    // ---- stationary W slice as u64 k-pairs ----
    u64 Wc0[32], Wc1[32];
    {
        const float* wbase = w_hh + (size_t)kb*Hq + j0 + jl*2;
        #pragma unroll
        for (int m = 0; m < 32; m++) {
            const float* wp = wbase + (size_t)(2*m)*Hq;
            Wc0[m] = packf2(wp[0], wp[Hq]);
            Wc1[m] = packf2(wp[1], wp[Hq + 1]);
        }
    }
    // ---- h seed into buffer 0 (chunked layout) ----
    for (int e = tid; e < NB*Hq; e += 256) {
        int b = e >> 9, k = e & 511;
        h_s[0][k >> 6][b][k & 63] = h_init[(size_t)(cid*NB + b)*h_stride + k];
    }
    const uint32_t mbar0  = smem_u32(&mbar_s[0][0]);
    const uint32_t hbase  = smem_u32(&h_s[0][0][0][0]);
    const uint32_t sbase  = smem_u32(&stage[0][0]);
    if (tid == 0) {
        #pragma unroll
        for (int i = 0; i < 2*CLU; i++) mbar_init(mbar0 + 8u*i, 1);
    }
    __syncthreads();
    asm volatile("barrier.cluster.arrive.aligned;" ::: "memory");
    asm volatile("barrier.cluster.wait.aligned;"   ::: "memory");

    const int fb = tid >> 6;                 // finisher batch (tid<128)
    const int fc = tid & 63;                 // finisher column (local)
    uint32_t dst_p = 0, mb_p = 0;
    if (tid < CLU) {
        dst_p = mapa_u32(hbase + (uint32_t)rank * CHUNK_B, (uint32_t)tid);
        mb_p  = mapa_u32(mbar0 + 8u*rank, (uint32_t)tid);
    }
    const bool is_pusher = (tid < CLU) && (tid != (int)rank);
    const float* xp_col = g_xp + (size_t)(cid*NB + fb)*Hq + j0 + fc;   // + g*Bq*Hq per step

    // ---- prefetch xp for the FIRST step ----
    float xpv = 0.f;
    if (tid < 128) xpv = __ldcg(xp_col + (size_t)t0*(Bq*Hq));

    for (int t = 0; t < tlen; t++) {
        const int g   = t0 + t;                 // global timestep
        const int cur = t & 1, nxt = cur ^ 1;
        // post expects for NEXT step's arrivals
        if (t < tlen - 1 && tid < CLU && tid != (int)rank)
            mbar_arrive_expect_tx(mbar0 + 8u*(nxt*CLU + tid), CHUNK_B);

        // prefetch xp for step t+1 (consumed next iteration -> DRAM latency fully hidden)
        float xpn = 0.f;
        if (tid < 128 && t < tlen - 1)
            xpn = __ldcg(xp_col + (size_t)(g + 1)*(Bq*Hq));

        // wait only for THIS warp's source chunk (own chunk written locally last step)
        if (t > 0 && s != (int)rank) {
            const uint32_t par = (uint32_t)(((t >> 1) - ((t & 1) ^ 1)) & 1);
            mbar_wait_parity(mbar0 + 8u*(cur*CLU + s), par);
        }

        // ---- GEMV: 2 batches x 2 cols over this warp's 64-k chunk ----
        const float* hb0 = &h_s[cur][s][0][0];
        const float* hb1 = &h_s[cur][s][1][0];
        u64 a00 = 0ull, a01 = 0ull, a10 = 0ull, a11 = 0ull;
        #pragma unroll
        for (int m = 0; m < 32; m++) {
            u64 h0 = *(const u64*)&hb0[2*m];   // broadcast LDS.64
            u64 h1 = *(const u64*)&hb1[2*m];
            a00 = ffma2(h0, Wc0[m], a00);
            a01 = ffma2(h0, Wc1[m], a01);
            a10 = ffma2(h1, Wc0[m], a10);
            a11 = ffma2(h1, Wc1[m], a11);
        }
        {
            float2 p00 = unpackf2(a00), p01 = unpackf2(a01);
            float2 p10 = unpackf2(a10), p11 = unpackf2(a11);
            *(float4*)&psum[0][kb + jl*2] = make_float4(p00.x, p00.y, p01.x, p01.y);
            *(float4*)&psum[1][kb + jl*2] = make_float4(p10.x, p10.y, p11.x, p11.y);
        }
        __syncthreads();

        // ---- finish: reduce 8 segments, sigmoid, store, stage outbound ----
        if (tid < 128) {
            float2 acc = psum[fb][fc];
            #pragma unroll
            for (int s2 = 1; s2 < 8; s2++) {
                float2 p = psum[fb][s2*64 + fc];
                acc.x += p.x; acc.y += p.y;
            }
            float v  = acc.x + acc.y + xpv;
            float hv = 1.f / (1.f + __expf(-v));
            const size_t bglob = (size_t)(cid*NB + fb);
            outbuf[RNN_OFF + bglob*Tq*Hq + (size_t)g*Hq + j0 + fc] = hv;
            if (g == Tq - 1) {
                outbuf[HN_OFF + bglob*Hq + j0 + fc] = hv;
            } else if (t < tlen - 1) {
                stage[nxt][fb*64 + fc] = hv;            // outbound
                h_s[nxt][rank][fb][fc] = hv;            // own chunk, local
            }
        }
        xpv = xpn;
        __syncthreads();   // psum reuse + stage/own-chunk visibility

        // ---- one 512B bulk copy per peer (7 threads issue in parallel) ----
        if (t < tlen - 1 && is_pusher) {
            fence_proxy_async_cta();
            bulk_copy_to_peer(dst_p + (uint32_t)(nxt * HSTRIDE),
                              sbase + (uint32_t)(nxt * CHUNK_B),
                              CHUNK_B,
                              mb_p + (uint32_t)(nxt * (CLU*8)));
        }
    }
}

// ---------------- fc1: hidden = relu(rnn_out @ fc1_w + b1), 64x64 tiles, u64 FFMA2 ----------------
__global__ void __launch_bounds__(256) fc1_kernel(const float* __restrict__ A,   // [32768, 512]
                                                  const float* __restrict__ W,   // [512, 512]
                                                  const float* __restrict__ bias) {
    __shared__ __align__(16) float  As[64*32];
    __shared__ __align__(16) float2 Ws2[16*64];
    const int tid = threadIdx.x;      // 256
    const int bx = blockIdx.x;
    const int by = blockIdx.y;
    const int tx = tid & 15, ty = tid >> 4;
    const int row0 = by*64, col0 = bx*64;

    u64 acc[4][4];
    #pragma unroll
    for (int i = 0; i < 4; i++)
        #pragma unroll
        for (int j = 0; j < 4; j++) acc[i][j] = 0ull;

    for (int kt = 0; kt < Hq; kt += 32) {
        {
            int r = tid >> 3, kq = (tid & 7) << 2;
            *(float4*)&As[r*32 + kq]      = *(const float4*)&A[(size_t)(row0 + r)*Hq + kt + kq];
            *(float4*)&As[(r+32)*32 + kq] = *(const float4*)&A[(size_t)(row0 + r + 32)*Hq + kt + kq];
            #pragma unroll
            for (int i = 0; i < 4; i++) {
                int u = tid + i*256;
                int kk = u >> 6, c = u & 63;
                const float* wp = &W[(size_t)(kt + 2*kk)*Hq + col0 + c];
                Ws2[kk*64 + c] = make_float2(wp[0], wp[Hq]);
            }
        }
        __syncthreads();
        #pragma unroll
        for (int kk = 0; kk < 16; kk++) {
            ulonglong2 wa = *(const ulonglong2*)&Ws2[kk*64 + tx*4];
            ulonglong2 wb = *(const ulonglong2*)&Ws2[kk*64 + tx*4 + 2];
            #pragma unroll
            for (int r4 = 0; r4 < 4; r4++) {
                u64 a2 = *(const u64*)&As[(ty*4 + r4)*32 + 2*kk];
                acc[r4][0] = ffma2(a2, wa.x, acc[r4][0]);
                acc[r4][1] = ffma2(a2, wa.y, acc[r4][1]);
                acc[r4][2] = ffma2(a2, wb.x, acc[r4][2]);
                acc[r4][3] = ffma2(a2, wb.y, acc[r4][3]);
            }
        }
        __syncthreads();
    }

    float4 bv = *(const float4*)&bias[col0 + tx*4];
    #pragma unroll
    for (int i = 0; i < 4; i++) {
        float4 o;
        o.x = fmaxf(hsum2(acc[i][0]) + bv.x, 0.f);
        o.y = fmaxf(hsum2(acc[i][1]) + bv.y, 0.f);
        o.z = fmaxf(hsum2(acc[i][2]) + bv.z, 0.f);
        o.w = fmaxf(hsum2(acc[i][3]) + bv.w, 0.f);
        *(float4*)&g_hidden[(size_t)(row0 + ty*4 + i)*Hq + col0 + tx*4] = o;
    }
}

// ---------------- fc2 ----------------
__global__ void fc2_kernel(const float* __restrict__ w2,
                           const float* __restrict__ b2,
                           float* __restrict__ out) {
    __shared__ float w2s[Hq*Aq];
    const int tid = threadIdx.x;   // 256
    for (int e = tid; e < Hq*Aq; e += 256) w2s[e] = w2[e];
    __syncthreads();

    const int r = tid >> 4;
    const int a = tid & 15;
    const size_t row = (size_t)blockIdx.x * 16 + r;
    const float* hrow = &g_hidden[row*Hq];

    float acc = 0.f;
    #pragma unroll 8
    for (int k = 0; k < Hq; k += 4) {
        float4 hv = *(const float4*)&hrow[k];
        acc = fmaf(hv.x, w2s[(k+0)*Aq + a], acc);
        acc = fmaf(hv.y, w2s[(k+1)*Aq + a], acc);
        acc = fmaf(hv.z, w2s[(k+2)*Aq + a], acc);
        acc = fmaf(hv.w, w2s[(k+3)*Aq + a], acc);
    }
    float v = acc + b2[a];
    out[row*Aq + a] = 1.f / (1.f + __expf(-v));
}

extern "C" void kernel_launch(void* const* d_in, const int* in_sizes, int n_in,
                              void* d_out, int out_size) {
    const float* inp  = (const float*)d_in[0];
    const float* hn   = (const float*)d_in[1];
    const float* w_hh = (const float*)d_in[2];
    const float* w_ih = (const float*)d_in[3];
    const float* fc1w = (const float*)d_in[4];
    const float* fc1b = (const float*)d_in[5];
    const float* fc2w = (const float*)d_in[6];
    const float* fc2b = (const float*)d_in[7];
    float* out = (float*)d_out;

    xp_kernel<<<dim3(32, 32), 512>>>(inp, w_ih);
    // half 1: steps [0,512), seeded from hn
    rnn_kernel<<<NCL*CLU, 256>>>(hn, (size_t)Hq, 0, 512, w_hh, out);
    // half 2: steps [512,1024), seeded from rnn_out[:, 511, :] (stride T*H)
    rnn_kernel<<<NCL*CLU, 256>>>(out + RNN_OFF + (size_t)511*Hq, (size_t)Tq*Hq, 512, 512, w_hh, out);
    fc1_kernel<<<dim3(8, 512), 256>>>(out + RNN_OFF, fc1w, fc1b);
    fc2_kernel<<<(Bq*Tq)/16, 256>>>(fc2w, fc2b, out);
}

// round 9
// speedup vs baseline: 1.9579x; 1.1864x over previous
#include <cuda_runtime.h>
#include <cstdint>

#define Bq 32
#define Tq 1024
#define Iq 64
#define Hq 512
#define Aq 16

#define OUT_N  (Bq*Tq*Aq)          // 524288
#define HN_N   (Bq*Hq)             // 16384
#define HN_OFF OUT_N
#define RNN_OFF (OUT_N + HN_N)     // 540672

#define CLU 8                      // CTAs per cluster
#define NCL 16                     // clusters (16*8 = 128 CTAs)
#define NB  2                      // batches per cluster
#define CHUNK_B 512                // bytes per source chunk
#define HSTRIDE (CLU*NB*64*4)      // bytes per h buffer (4096)

typedef unsigned long long u64;

// ---- scratch (static device globals: allocation-free) ----
__device__ float g_xp[Tq*Bq*Hq];               // x_proj [t][b][j]   (64 MB)
__device__ float g_hidden[(size_t)Bq*Tq*Hq];   // fc1 output (64 MB)

// ================= helpers =================
__device__ __forceinline__ uint32_t smem_u32(const void* p) {
    uint32_t a;
    asm("{ .reg .u64 t; cvta.to.shared.u64 t, %1; cvt.u32.u64 %0, t; }" : "=r"(a) : "l"(p));
    return a;
}
__device__ __forceinline__ uint32_t mapa_u32(uint32_t laddr, uint32_t rank) {
    uint32_t r;
    asm("mapa.shared::cluster.u32 %0, %1, %2;" : "=r"(r) : "r"(laddr), "r"(rank));
    return r;
}
__device__ __forceinline__ void mbar_init(uint32_t mbar, uint32_t cnt) {
    asm volatile("mbarrier.init.shared.b64 [%0], %1;" :: "r"(mbar), "r"(cnt) : "memory");
}
__device__ __forceinline__ void mbar_arrive_expect_tx(uint32_t mbar, uint32_t tx) {
    asm volatile("mbarrier.arrive.expect_tx.shared.b64 _, [%0], %1;" :: "r"(mbar), "r"(tx) : "memory");
}
__device__ __forceinline__ void mbar_wait_parity(uint32_t mbar, uint32_t parity) {
    asm volatile(
        "{\n\t"
        ".reg .pred P1;\n\t"
        "WAIT_LOOP_%=:\n\t"
        "mbarrier.try_wait.parity.acquire.cta.shared::cta.b64 P1, [%0], %1, 0x989680;\n\t"
        "@P1 bra.uni WAIT_DONE_%=;\n\t"
        "bra.uni WAIT_LOOP_%=;\n\t"
        "WAIT_DONE_%=:\n\t"
        "}" :: "r"(mbar), "r"(parity) : "memory");
}
__device__ __forceinline__ void bulk_copy_to_peer(uint32_t dst_cluster, uint32_t src_cta,
                                                  uint32_t bytes, uint32_t rmbar_cluster) {
    asm volatile(
        "cp.async.bulk.shared::cluster.shared::cta.mbarrier::complete_tx::bytes [%0], [%1], %2, [%3];"
        :: "r"(dst_cluster), "r"(src_cta), "r"(bytes), "r"(rmbar_cluster) : "memory");
}
__device__ __forceinline__ void fence_proxy_async_cta() {
    asm volatile("fence.proxy.async.shared::cta;" ::: "memory");
}
__device__ __forceinline__ u64 ffma2(u64 a, u64 b, u64 c) {
    u64 d;
    asm("fma.rn.f32x2 %0, %1, %2, %3;" : "=l"(d) : "l"(a), "l"(b), "l"(c));
    return d;
}
__device__ __forceinline__ u64 packf2(float x, float y) {
    u64 r; asm("mov.b64 %0, {%1,%2};" : "=l"(r) : "f"(x), "f"(y)); return r;
}
__device__ __forceinline__ float2 unpackf2(u64 v) {
    float2 f; asm("mov.b64 {%0,%1}, %2;" : "=f"(f.x), "=f"(f.y) : "l"(v)); return f;
}
__device__ __forceinline__ uint32_t cvt_tf32(float f) {
    uint32_t r; asm("cvt.rna.tf32.f32 %0, %1;" : "=r"(r) : "f"(f)); return r;
}
__device__ __forceinline__ void ldsm_x4(uint32_t& d0, uint32_t& d1, uint32_t& d2, uint32_t& d3,
                                        uint32_t addr) {
    asm volatile("ldmatrix.sync.aligned.m8n8.x4.shared.b16 {%0,%1,%2,%3}, [%4];"
                 : "=r"(d0), "=r"(d1), "=r"(d2), "=r"(d3) : "r"(addr));
}
__device__ __forceinline__ void mma_tf32(float& c0, float& c1, float& c2, float& c3,
                                         uint32_t a0, uint32_t a1, uint32_t a2, uint32_t a3,
                                         uint32_t b0, uint32_t b1) {
    asm volatile("mma.sync.aligned.m16n8k8.row.col.f32.tf32.tf32.f32 "
                 "{%0,%1,%2,%3}, {%4,%5,%6,%7}, {%8,%9}, {%0,%1,%2,%3};"
                 : "+f"(c0), "+f"(c1), "+f"(c2), "+f"(c3)
                 : "r"(a0), "r"(a1), "r"(a2), "r"(a3), "r"(b0), "r"(b1));
}

// ---------------- x_proj ----------------
__global__ void xp_kernel(const float* __restrict__ inp, const float* __restrict__ w_ih) {
    const int b   = blockIdx.x;
    const int tc  = blockIdx.y;
    const int tid = threadIdx.x;  // 512
    __shared__ float s_in[32*64];
    const float* src = inp + (size_t)b*Tq*Iq + (size_t)tc*32*Iq;
    ((float4*)s_in)[tid] = ((const float4*)src)[tid];
    __syncthreads();

    float acc[32];
    #pragma unroll
    for (int tt = 0; tt < 32; tt++) acc[tt] = 0.f;
    #pragma unroll 8
    for (int i = 0; i < Iq; i++) {
        float w = w_ih[i*Hq + tid];
        #pragma unroll
        for (int tt = 0; tt < 32; tt++)
            acc[tt] = fmaf(s_in[tt*64 + i], w, acc[tt]);
    }
    #pragma unroll
    for (int tt = 0; tt < 32; tt++)
        g_xp[(size_t)(tc*32 + tt)*(Bq*Hq) + b*Hq + tid] = acc[tt];
}

// ---------------- RNN scan (half-range launch) — unchanged from R8 ----------------
__global__ void __launch_bounds__(256, 1) __cluster_dims__(CLU, 1, 1)
rnn_kernel(const float* __restrict__ h_init, size_t h_stride, int t0, int tlen,
           const float* __restrict__ w_hh, float* __restrict__ outbuf) {
    __shared__ __align__(16) float  h_s[2][CLU][NB][64];
    __shared__ __align__(16) float  stage[2][NB*64];
    __shared__ __align__(16) float2 psum[NB][512];
    __shared__ __align__(8)  unsigned long long mbar_s[2][CLU];

    const int tid = threadIdx.x;
    uint32_t rank;
    asm("mov.u32 %0, %%cluster_ctarank;" : "=r"(rank));
    const int cid = blockIdx.x >> 3;
    const int j0  = (int)rank * 64;
    const int s   = tid >> 5;
    const int jl  = tid & 31;
    const int kb  = s * 64;

    u64 Wc0[32], Wc1[32];
    {
        const float* wbase = w_hh + (size_t)kb*Hq + j0 + jl*2;
        #pragma unroll
        for (int m = 0; m < 32; m++) {
            const float* wp = wbase + (size_t)(2*m)*Hq;
            Wc0[m] = packf2(wp[0], wp[Hq]);
            Wc1[m] = packf2(wp[1], wp[Hq + 1]);
        }
    }
    for (int e = tid; e < NB*Hq; e += 256) {
        int b = e >> 9, k = e & 511;
        h_s[0][k >> 6][b][k & 63] = h_init[(size_t)(cid*NB + b)*h_stride + k];
    }
    const uint32_t mbar0  = smem_u32(&mbar_s[0][0]);
    const uint32_t hbase  = smem_u32(&h_s[0][0][0][0]);
    const uint32_t sbase  = smem_u32(&stage[0][0]);
    if (tid == 0) {
        #pragma unroll
        for (int i = 0; i < 2*CLU; i++) mbar_init(mbar0 + 8u*i, 1);
    }
    __syncthreads();
    asm volatile("barrier.cluster.arrive.aligned;" ::: "memory");
    asm volatile("barrier.cluster.wait.aligned;"   ::: "memory");

    const int fb = tid >> 6;
    const int fc = tid & 63;
    uint32_t dst_p = 0, mb_p = 0;
    if (tid < CLU) {
        dst_p = mapa_u32(hbase + (uint32_t)rank * CHUNK_B, (uint32_t)tid);
        mb_p  = mapa_u32(mbar0 + 8u*rank, (uint32_t)tid);
    }
    const bool is_pusher = (tid < CLU) && (tid != (int)rank);
    const float* xp_col = g_xp + (size_t)(cid*NB + fb)*Hq + j0 + fc;

    float xpv = 0.f;
    if (tid < 128) xpv = __ldcg(xp_col + (size_t)t0*(Bq*Hq));

    for (int t = 0; t < tlen; t++) {
        const int g   = t0 + t;
        const int cur = t & 1, nxt = cur ^ 1;
        if (t < tlen - 1 && tid < CLU && tid != (int)rank)
            mbar_arrive_expect_tx(mbar0 + 8u*(nxt*CLU + tid), CHUNK_B);

        float xpn = 0.f;
        if (tid < 128 && t < tlen - 1)
            xpn = __ldcg(xp_col + (size_t)(g + 1)*(Bq*Hq));

        if (t > 0 && s != (int)rank) {
            const uint32_t par = (uint32_t)(((t >> 1) - ((t & 1) ^ 1)) & 1);
            mbar_wait_parity(mbar0 + 8u*(cur*CLU + s), par);
        }

        const float* hb0 = &h_s[cur][s][0][0];
        const float* hb1 = &h_s[cur][s][1][0];
        u64 a00 = 0ull, a01 = 0ull, a10 = 0ull, a11 = 0ull;
        #pragma unroll
        for (int m = 0; m < 32; m++) {
            u64 h0 = *(const u64*)&hb0[2*m];
            u64 h1 = *(const u64*)&hb1[2*m];
            a00 = ffma2(h0, Wc0[m], a00);
            a01 = ffma2(h0, Wc1[m], a01);
            a10 = ffma2(h1, Wc0[m], a10);
            a11 = ffma2(h1, Wc1[m], a11);
        }
        {
            float2 p00 = unpackf2(a00), p01 = unpackf2(a01);
            float2 p10 = unpackf2(a10), p11 = unpackf2(a11);
            *(float4*)&psum[0][kb + jl*2] = make_float4(p00.x, p00.y, p01.x, p01.y);
            *(float4*)&psum[1][kb + jl*2] = make_float4(p10.x, p10.y, p11.x, p11.y);
        }
        __syncthreads();

        if (tid < 128) {
            float2 acc = psum[fb][fc];
            #pragma unroll
            for (int s2 = 1; s2 < 8; s2++) {
                float2 p = psum[fb][s2*64 + fc];
                acc.x += p.x; acc.y += p.y;
            }
            float v  = acc.x + acc.y + xpv;
            float hv = 1.f / (1.f + __expf(-v));
            const size_t bglob = (size_t)(cid*NB + fb);
            outbuf[RNN_OFF + bglob*Tq*Hq + (size_t)g*Hq + j0 + fc] = hv;
            if (g == Tq - 1) {
                outbuf[HN_OFF + bglob*Hq + j0 + fc] = hv;
            } else if (t < tlen - 1) {
                stage[nxt][fb*64 + fc] = hv;
                h_s[nxt][rank][fb][fc] = hv;
            }
        }
        xpv = xpn;
        __syncthreads();

        if (t < tlen - 1 && is_pusher) {
            fence_proxy_async_cta();
            bulk_copy_to_peer(dst_p + (uint32_t)(nxt * HSTRIDE),
                              sbase + (uint32_t)(nxt * CHUNK_B),
                              CHUNK_B,
                              mb_p + (uint32_t)(nxt * (CLU*8)));
        }
    }
}

// ---------------- fc1: tf32 mma.sync GEMM, CTA 128x128, warp 64x32 ----------------
// A [32768,512] row-major, W [512,512] row-major ([k][col]); B staged TRANSPOSED [n][k]
// so both operand fragments load via ldmatrix.x4 (b16 trick: 1 tf32 = 2 b16).
// Rows padded to 12 floats (48B) -> the 8 LDSM row windows hit disjoint bank groups.
#define FM 128
#define FN 128
#define PAD 12
__global__ void __launch_bounds__(256, 1)
fc1_kernel(const float* __restrict__ A, const float* __restrict__ W,
           const float* __restrict__ bias) {
    __shared__ __align__(16) uint32_t As[2][FM][PAD];   // 12 KB
    __shared__ __align__(16) uint32_t Bs[2][FN][PAD];   // 12 KB

    const int tid  = threadIdx.x;      // 256
    const int wid  = tid >> 5, lane = tid & 31;
    const int row0 = blockIdx.y * FM;  // 256 row tiles
    const int col0 = blockIdx.x * FN;  // 4 col tiles
    const int wm   = wid >> 2;         // warp 64-row half (0..1)
    const int wn   = wid & 3;          // warp 32-col quarter (0..3)

    // gmem staging indices
    const int arow = tid >> 1, akq = (tid & 1) * 4;   // A: LDG.128, 128 rows x 8k
    const int bk   = tid >> 5, bc  = (tid & 31) * 4;  // W: LDG.128, 8 k-rows x 128 cols

    // ldmatrix source addresses (byte, within buffer 0)
    const uint32_t as0 = smem_u32(&As[0][0][0]);
    const uint32_t bs0 = smem_u32(&Bs[0][0][0]);
    const uint32_t a_off = ((uint32_t)((wm*64 + (lane & 15))*PAD + (lane >> 4)*4)) * 4u;
    const uint32_t b_off = ((uint32_t)((wn*32 + (lane & 7) + ((lane >> 4) & 1)*8)*PAD
                                       + ((lane >> 3) & 1)*4)) * 4u;
    const uint32_t BUFB = FM * PAD * 4u;   // bytes per buffer

    float c[4][4][4];
    #pragma unroll
    for (int mt = 0; mt < 4; mt++)
        #pragma unroll
        for (int nt = 0; nt < 4; nt++)
            #pragma unroll
            for (int i = 0; i < 4; i++) c[mt][nt][i] = 0.f;

    // preload k-step 0
    uint4 ar; uint4 br;
    {
        float4 a4 = *(const float4*)&A[(size_t)(row0 + arow)*Hq + akq];
        float4 b4 = *(const float4*)&W[(size_t)bk*Hq + col0 + bc];
        ar = make_uint4(cvt_tf32(a4.x), cvt_tf32(a4.y), cvt_tf32(a4.z), cvt_tf32(a4.w));
        br = make_uint4(cvt_tf32(b4.x), cvt_tf32(b4.y), cvt_tf32(b4.z), cvt_tf32(b4.w));
    }

    for (int ks = 0; ks < 64; ks++) {
        const int buf = ks & 1;
        // stage current k-slice
        *(uint4*)&As[buf][arow][akq] = ar;
        Bs[buf][bc + 0][bk] = br.x;
        Bs[buf][bc + 1][bk] = br.y;
        Bs[buf][bc + 2][bk] = br.z;
        Bs[buf][bc + 3][bk] = br.w;
        // prefetch next k-slice
        if (ks < 63) {
            const int kt = (ks + 1) * 8;
            float4 a4 = *(const float4*)&A[(size_t)(row0 + arow)*Hq + kt + akq];
            float4 b4 = *(const float4*)&W[(size_t)(kt + bk)*Hq + col0 + bc];
            ar = make_uint4(cvt_tf32(a4.x), cvt_tf32(a4.y), cvt_tf32(a4.z), cvt_tf32(a4.w));
            br = make_uint4(cvt_tf32(b4.x), cvt_tf32(b4.y), cvt_tf32(b4.z), cvt_tf32(b4.w));
        }
        __syncthreads();

        // fragments
        uint32_t af[4][4], bf[4][2];
        #pragma unroll
        for (int mt = 0; mt < 4; mt++)
            ldsm_x4(af[mt][0], af[mt][1], af[mt][2], af[mt][3],
                    as0 + buf*BUFB + a_off + (uint32_t)(mt*16*PAD*4));
        #pragma unroll
        for (int np = 0; np < 2; np++)
            ldsm_x4(bf[2*np][0], bf[2*np][1], bf[2*np + 1][0], bf[2*np + 1][1],
                    bs0 + buf*BUFB + b_off + (uint32_t)(np*16*PAD*4));

        #pragma unroll
        for (int mt = 0; mt < 4; mt++)
            #pragma unroll
            for (int nt = 0; nt < 4; nt++)
                mma_tf32(c[mt][nt][0], c[mt][nt][1], c[mt][nt][2], c[mt][nt][3],
                         af[mt][0], af[mt][1], af[mt][2], af[mt][3],
                         bf[nt][0], bf[nt][1]);
    }

    // epilogue: bias + relu, STG.64 pairs
    const int gq = lane >> 2, tq = lane & 3;
    #pragma unroll
    for (int nt = 0; nt < 4; nt++) {
        const int cb = col0 + wn*32 + nt*8 + 2*tq;
        const float2 bv = *(const float2*)&bias[cb];
        #pragma unroll
        for (int mt = 0; mt < 4; mt++) {
            const int r0 = row0 + wm*64 + mt*16 + gq;
            float2 o0, o1;
            o0.x = fmaxf(c[mt][nt][0] + bv.x, 0.f);
            o0.y = fmaxf(c[mt][nt][1] + bv.y, 0.f);
            o1.x = fmaxf(c[mt][nt][2] + bv.x, 0.f);
            o1.y = fmaxf(c[mt][nt][3] + bv.y, 0.f);
            *(float2*)&g_hidden[(size_t)r0*Hq + cb]       = o0;
            *(float2*)&g_hidden[(size_t)(r0 + 8)*Hq + cb] = o1;
        }
    }
}

// ---------------- fc2 ----------------
__global__ void fc2_kernel(const float* __restrict__ w2,
                           const float* __restrict__ b2,
                           float* __restrict__ out) {
    __shared__ float w2s[Hq*Aq];
    const int tid = threadIdx.x;   // 256
    for (int e = tid; e < Hq*Aq; e += 256) w2s[e] = w2[e];
    __syncthreads();

    const int r = tid >> 4;
    const int a = tid & 15;
    const size_t row = (size_t)blockIdx.x * 16 + r;
    const float* hrow = &g_hidden[row*Hq];

    float acc = 0.f;
    #pragma unroll 8
    for (int k = 0; k < Hq; k += 4) {
        float4 hv = *(const float4*)&hrow[k];
        acc = fmaf(hv.x, w2s[(k+0)*Aq + a], acc);
        acc = fmaf(hv.y, w2s[(k+1)*Aq + a], acc);
        acc = fmaf(hv.z, w2s[(k+2)*Aq + a], acc);
        acc = fmaf(hv.w, w2s[(k+3)*Aq + a], acc);
    }
    float v = acc + b2[a];
    out[row*Aq + a] = 1.f / (1.f + __expf(-v));
}

extern "C" void kernel_launch(void* const* d_in, const int* in_sizes, int n_in,
                              void* d_out, int out_size) {
    const float* inp  = (const float*)d_in[0];
    const float* hn   = (const float*)d_in[1];
    const float* w_hh = (const float*)d_in[2];
    const float* w_ih = (const float*)d_in[3];
    const float* fc1w = (const float*)d_in[4];
    const float* fc1b = (const float*)d_in[5];
    const float* fc2w = (const float*)d_in[6];
    const float* fc2b = (const float*)d_in[7];
    float* out = (float*)d_out;

    xp_kernel<<<dim3(32, 32), 512>>>(inp, w_ih);
    rnn_kernel<<<NCL*CLU, 256>>>(hn, (size_t)Hq, 0, 512, w_hh, out);
    rnn_kernel<<<NCL*CLU, 256>>>(out + RNN_OFF + (size_t)511*Hq, (size_t)Tq*Hq, 512, 512, w_hh, out);
    fc1_kernel<<<dim3(4, 256), 256>>>(out + RNN_OFF, fc1w, fc1b);
    fc2_kernel<<<(Bq*Tq)/16, 256>>>(fc2w, fc2b, out);
}